// round 13
// baseline (speedup 1.0000x reference)
#include <cuda_runtime.h>
#include <cstdint>

// Problem constants
#define N_   5000
#define D_   128
#define T_   100
#define K_   20
#define KH   10            // half-K pipeline granularity
#define EPSV 1e-8f
#define KT_  (K_ * T_)

// GEMM tiling
#define NT 16
#define DT 16
#define TC 32
#define TPAD 36            // padded t-row (36 floats = 144B, 16B-aligned)
#define NTB 256
#define NTILES 313         // ceil(5000/16)
#define ZSPLIT 9           // 8 x 4 x 9 = 288 blocks = one wave @ 2/SM
#define STEPS  35          // ceil(313/9)

// smem: thA/thB [KH][NT][TPAD] f32 + ph [K][DT][TPAD] f32 + ev [NT][DT] int
#define TH_HALF_F  (KH * NT * TPAD)         // 5760 floats (23040 B)
#define PH_F       (K_ * DT * TPAD)         // 11520 floats (46080 B)
#define SMEM_BYTES (TH_HALF_F * 4 * 2 + PH_F * 4 + NT * DT * 4)

__device__ float g_phip_scratch[K_ * D_ * T_];
__device__ float g_theta_scratch[N_ * K_ * T_];

// ---- cp.async helpers ----
__device__ __forceinline__ void cpa16(uint32_t d, const float* s, bool p) {
    asm volatile("cp.async.cg.shared.global [%0], [%1], 16, %2;"
                 :: "r"(d), "l"(s), "r"(p ? 16 : 0));
}
__device__ __forceinline__ void cpa4(uint32_t d, const int* s, bool p) {
    asm volatile("cp.async.ca.shared.global [%0], [%1], 4, %2;"
                 :: "r"(d), "l"(s), "r"(p ? 4 : 0));
}
#define CPCOMMIT() asm volatile("cp.async.commit_group;")
#define CPWAIT0()  asm volatile("cp.async.wait_group 0;")

// ---------------------------------------------------------------------------
// Kernel 1: phi_prob = sigmoid(phi)
// ---------------------------------------------------------------------------
__global__ void sigmoid_kernel(const float4* __restrict__ phi,
                               float4* __restrict__ out) {
    int i = blockIdx.x * blockDim.x + threadIdx.x;
    if (i < (K_ * D_ * T_) / 4) {
        float4 v = phi[i];
        v.x = __fdividef(1.0f, 1.0f + __expf(-v.x));
        v.y = __fdividef(1.0f, 1.0f + __expf(-v.y));
        v.z = __fdividef(1.0f, 1.0f + __expf(-v.z));
        v.w = __fdividef(1.0f, 1.0f + __expf(-v.w));
        out[i] = v;
    }
}

// ---------------------------------------------------------------------------
// Kernel 2: theta = softmax_K(lambda)
// ---------------------------------------------------------------------------
__global__ __launch_bounds__(256)
void softmax_kernel(const float* __restrict__ lam,
                    float* __restrict__ theta) {
    int idx = blockIdx.x * 256 + threadIdx.x;
    if (idx >= N_ * T_) return;
    int n = idx / T_;
    int t = idx - n * T_;
    const float* src = lam + n * KT_ + t;
    float v[K_];
    #pragma unroll
    for (int k = 0; k < K_; ++k) v[k] = src[k * T_];
    float m = v[0];
    #pragma unroll
    for (int k = 1; k < K_; ++k) m = fmaxf(m, v[k]);
    float s = 0.0f;
    #pragma unroll
    for (int k = 0; k < K_; ++k) { v[k] = __expf(v[k] - m); s += v[k]; }
    float inv = __fdividef(1.0f, s);
    float* dst = theta + n * KT_ + t;
    #pragma unroll
    for (int k = 0; k < K_; ++k) dst[k * T_] = v[k] * inv;
}

// ---------------------------------------------------------------------------
// Kernel 3: pi = clip(mask * (theta @ phi_prob))
//   t-quad vectorized: thread owns 4 consecutive t -> LDS.128 operands,
//   f32x2 FMA pairs over t, STG.128 stores. cp.async half-K pipeline.
//   Thread tile: 4n x 2d x 4t. Warp: lane = s*8+q (s->d-subgroup, q->t-quad).
// ---------------------------------------------------------------------------
__global__ __launch_bounds__(NTB, 2)
void gemm_kernel(const float* __restrict__ theta_g,
                 const float* __restrict__ phip,
                 const int*   __restrict__ evt,
                 float*       __restrict__ pi) {
    extern __shared__ float smem[];
    float* s_thA = smem;                          // [KH][NT][TPAD]
    float* s_thB = smem + TH_HALF_F;              // [KH][NT][TPAD]
    float* s_ph  = smem + 2 * TH_HALF_F;          // [K][DT][TPAD]
    int*   s_ev  = (int*)(smem + 2 * TH_HALF_F + PH_F);  // [NT][DT]

    const uint32_t u_thA = (uint32_t)__cvta_generic_to_shared(s_thA);
    const uint32_t u_thB = (uint32_t)__cvta_generic_to_shared(s_thB);
    const uint32_t u_ev  = (uint32_t)__cvta_generic_to_shared(s_ev);

    const int tid = threadIdx.x;
    const int d0 = blockIdx.x * DT;
    const int t0 = blockIdx.y * TC;

    // ---- phi tile: load once. 20k x 16d x 8 quads = 2560 chunks ----
    #pragma unroll
    for (int r = 0; r < 10; ++r) {
        int f  = tid + r * NTB;          // 0..2559
        int j  = f & 7;
        int dd = (f >> 3) & 15;
        int k  = f >> 7;                 // 0..19
        int t  = t0 + 4 * j;
        float4 v = make_float4(0.f, 0.f, 0.f, 0.f);
        if (t < T_)
            v = *reinterpret_cast<const float4*>(
                    phip + k * (D_ * T_) + (d0 + dd) * T_ + t);
        *reinterpret_cast<float4*>(&s_ph[(k * DT + dd) * TPAD + 4 * j]) = v;
    }

    // ---- theta cp.async descriptors (5 x 16B per thread per half) ----
    int      cni[5], coff[5];
    uint32_t cdst[5];
    bool     ctv[5];
    #pragma unroll
    for (int r = 0; r < 5; ++r) {
        int f  = tid + r * NTB;          // 0..1279
        int j  = f & 7;
        int ni = (f >> 3) & 15;
        int kk = f >> 7;                 // 0..9
        int tt = t0 + 4 * j;
        cni[r]  = ni;
        ctv[r]  = (tt < T_);
        coff[r] = ni * KT_ + kk * T_ + tt;
        cdst[r] = ((kk * NT + ni) * TPAD + 4 * j) * 4;
    }
    // evt descriptor: 256 cells, one per thread
    const int eni = tid >> 4;
    const int edd = tid & 15;

    const int w    = tid >> 5;
    const int lane = tid & 31;
    const int s    = lane >> 3;      // 0..3 -> d-subgroup
    const int q    = lane & 7;       // 0..7 -> t-quad
    const int nb   = (w >> 1) * 4;   // n base: 0,4,8,12
    const int db   = (w & 1) * 8 + s * 2;  // local d base (2 d per thread)
    const int tq   = 4 * q;          // quad base within chunk
    const int tb   = t0 + tq;        // global quad base
    const bool qv  = (tb < T_);      // whole quad valid (T=100 -> never straddles)

    // ---- prologue: issue A(s=0) ----
    {
        int n0 = blockIdx.z * STEPS * NT;
        #pragma unroll
        for (int r = 0; r < 5; ++r)
            cpa16(u_thA + cdst[r], theta_g + n0 * KT_ + coff[r],
                  (n0 + cni[r] < N_) && ctv[r]);
        CPCOMMIT();
    }

    for (int st = 0; st < STEPS; ++st) {
        int nt = blockIdx.z * STEPS + st;
        if (nt >= NTILES) break;
        int n0 = nt * NT;

        CPWAIT0();           // A(st) ready
        __syncthreads();     // prior GEMM-B done with B buffer

        // issue B(st) (k=10..19) + evt(st)
        #pragma unroll
        for (int r = 0; r < 5; ++r)
            cpa16(u_thB + cdst[r], theta_g + n0 * KT_ + coff[r] + KH * T_,
                  (n0 + cni[r] < N_) && ctv[r]);
        cpa4(u_ev + (eni * DT + edd) * 4,
             evt + (size_t)(n0 + eni) * D_ + d0 + edd,
             n0 + eni < N_);
        CPCOMMIT();

        unsigned long long acc[4][2][2];
        #pragma unroll
        for (int i = 0; i < 4; ++i)
            #pragma unroll
            for (int jd = 0; jd < 2; ++jd) {
                acc[i][jd][0] = 0ULL; acc[i][jd][1] = 0ULL;
            }

        // ---- GEMM half A: k = 0..9 ----
        #pragma unroll
        for (int kh = 0; kh < KH; ++kh) {
            ulonglong2 b0 = *reinterpret_cast<const ulonglong2*>(
                &s_ph[(kh * DT + db) * TPAD + tq]);
            ulonglong2 b1 = *reinterpret_cast<const ulonglong2*>(
                &s_ph[(kh * DT + db + 1) * TPAD + tq]);
            #pragma unroll
            for (int i = 0; i < 4; ++i) {
                ulonglong2 a = *reinterpret_cast<const ulonglong2*>(
                    &s_thA[(kh * NT + nb + i) * TPAD + tq]);
                asm("fma.rn.f32x2 %0, %1, %2, %0;" : "+l"(acc[i][0][0]) : "l"(a.x), "l"(b0.x));
                asm("fma.rn.f32x2 %0, %1, %2, %0;" : "+l"(acc[i][0][1]) : "l"(a.y), "l"(b0.y));
                asm("fma.rn.f32x2 %0, %1, %2, %0;" : "+l"(acc[i][1][0]) : "l"(a.x), "l"(b1.x));
                asm("fma.rn.f32x2 %0, %1, %2, %0;" : "+l"(acc[i][1][1]) : "l"(a.y), "l"(b1.y));
            }
        }

        CPWAIT0();           // B(st) + evt ready
        __syncthreads();     // all warps done with A buffer

        // issue A(st+1)
        {
            int n0n = n0 + NT;
            #pragma unroll
            for (int r = 0; r < 5; ++r)
                cpa16(u_thA + cdst[r], theta_g + n0n * KT_ + coff[r],
                      (n0n + cni[r] < N_) && ctv[r]);
            CPCOMMIT();
        }

        // ---- GEMM half B: k = 10..19 ----
        #pragma unroll
        for (int kh = 0; kh < KH; ++kh) {
            ulonglong2 b0 = *reinterpret_cast<const ulonglong2*>(
                &s_ph[((KH + kh) * DT + db) * TPAD + tq]);
            ulonglong2 b1 = *reinterpret_cast<const ulonglong2*>(
                &s_ph[((KH + kh) * DT + db + 1) * TPAD + tq]);
            #pragma unroll
            for (int i = 0; i < 4; ++i) {
                ulonglong2 a = *reinterpret_cast<const ulonglong2*>(
                    &s_thB[(kh * NT + nb + i) * TPAD + tq]);
                asm("fma.rn.f32x2 %0, %1, %2, %0;" : "+l"(acc[i][0][0]) : "l"(a.x), "l"(b0.x));
                asm("fma.rn.f32x2 %0, %1, %2, %0;" : "+l"(acc[i][0][1]) : "l"(a.y), "l"(b0.y));
                asm("fma.rn.f32x2 %0, %1, %2, %0;" : "+l"(acc[i][1][0]) : "l"(a.x), "l"(b1.x));
                asm("fma.rn.f32x2 %0, %1, %2, %0;" : "+l"(acc[i][1][1]) : "l"(a.y), "l"(b1.y));
            }
        }

        // ---- epilogue: mask, clip, STG.128 streaming stores ----
        if (qv) {
            #pragma unroll
            for (int i = 0; i < 4; ++i) {
                int n = n0 + nb + i;
                if (n >= N_) continue;
                int2 e = *reinterpret_cast<const int2*>(&s_ev[(nb + i) * DT + db]);
                float* prow = pi + (size_t)n * (D_ * T_);
                #pragma unroll
                for (int jd = 0; jd < 2; ++jd) {
                    int   es = jd ? e.y : e.x;
                    float f0, f1, f2, f3;
                    asm("mov.b64 {%0, %1}, %2;" : "=f"(f0), "=f"(f1) : "l"(acc[i][jd][0]));
                    asm("mov.b64 {%0, %1}, %2;" : "=f"(f2), "=f"(f3) : "l"(acc[i][jd][1]));
                    f0 = (tb + 0 <= es) ? f0 : 0.0f;
                    f1 = (tb + 1 <= es) ? f1 : 0.0f;
                    f2 = (tb + 2 <= es) ? f2 : 0.0f;
                    f3 = (tb + 3 <= es) ? f3 : 0.0f;
                    f0 = fminf(fmaxf(f0, EPSV), 1.0f - EPSV);
                    f1 = fminf(fmaxf(f1, EPSV), 1.0f - EPSV);
                    f2 = fminf(fmaxf(f2, EPSV), 1.0f - EPSV);
                    f3 = fminf(fmaxf(f3, EPSV), 1.0f - EPSV);
                    float4 vv = make_float4(f0, f1, f2, f3);
                    __stcs(reinterpret_cast<float4*>(
                               &prow[(d0 + db + jd) * T_ + tb]), vv);
                }
            }
        }
    }
    CPWAIT0();   // drain stray prefetch before CTA exit
}

// ---------------------------------------------------------------------------
// Launch
// ---------------------------------------------------------------------------
extern "C" void kernel_launch(void* const* d_in, const int* in_sizes, int n_in,
                              void* d_out, int out_size) {
    const float* lam = (const float*)d_in[0];  // [N,K,T] f32
    const float* phi = (const float*)d_in[1];  // [K,D,T] f32
    const int*   evt = (const int*)d_in[2];    // [N,D]   i32

    const long long PI_SZ  = (long long)N_ * D_ * T_;
    const long long TH_SZ  = (long long)N_ * K_ * T_;
    const long long PHP_SZ = (long long)K_ * D_ * T_;

    float* out   = (float*)d_out;
    float* pi    = out;
    float* theta = out + PI_SZ;
    float* phip  = out + PI_SZ + TH_SZ;

    const long long osz = (long long)out_size;
    if (osz < PI_SZ + TH_SZ)
        cudaGetSymbolAddress((void**)&theta, g_theta_scratch);
    if (osz < PI_SZ + TH_SZ + PHP_SZ)
        cudaGetSymbolAddress((void**)&phip, g_phip_scratch);

    // 1) phi_prob = sigmoid(phi)
    int nvec = (K_ * D_ * T_) / 4;
    sigmoid_kernel<<<(nvec + 255) / 256, 256>>>((const float4*)phi,
                                                (float4*)phip);

    // 2) theta = softmax(lambda)
    int npts = N_ * T_;
    softmax_kernel<<<(npts + 255) / 256, 256>>>(lam, theta);

    // 3) pi = mask*clip(theta @ phi_prob)
    cudaFuncSetAttribute(gemm_kernel,
                         cudaFuncAttributeMaxDynamicSharedMemorySize,
                         SMEM_BYTES);
    dim3 grid(D_ / DT, (T_ + TC - 1) / TC, ZSPLIT);  // 8 x 4 x 9 = 288
    gemm_kernel<<<grid, NTB, SMEM_BYTES>>>(theta, phip, evt, pi);
}

// round 14
// speedup vs baseline: 1.3534x; 1.3534x over previous
#include <cuda_runtime.h>
#include <cstdint>

// Problem constants
#define N_   5000
#define D_   128
#define T_   100
#define K_   20
#define KQ   5             // quarter-K pipeline granularity
#define EPSV 1e-8f
#define KT_  (K_ * T_)

// GEMM tiling
#define NT 16
#define DT 16
#define TC 32
#define NTB 256
#define NTILES 313         // ceil(5000/16)
#define ZSPLIT 13          // 8 x 4 x 13 = 416 blocks ~ one wave @ 3/SM
#define STEPS  25

// smem: thA/thB [KQ][NT][TC] f32 (10KB each) + ph [K][DT/2][TC] f2 (40KB) + ev
#define TH_Q_F (KQ * NT * TC)            // 2560 floats
#define PH_F2  (K_ * (DT / 2) * TC)      // 5120 float2
#define SMEM_BYTES (TH_Q_F * 4 * 2 + PH_F2 * 8 + NT * DT * 4)   // ~62.5KB

__device__ float g_phip_scratch[K_ * D_ * T_];
__device__ float g_theta_scratch[N_ * K_ * T_];

// ---- cp.async helpers ----
__device__ __forceinline__ void cpa16(uint32_t d, const float* s, bool p) {
    asm volatile("cp.async.cg.shared.global [%0], [%1], 16, %2;"
                 :: "r"(d), "l"(s), "r"(p ? 16 : 0));
}
__device__ __forceinline__ void cpa4(uint32_t d, const int* s, bool p) {
    asm volatile("cp.async.ca.shared.global [%0], [%1], 4, %2;"
                 :: "r"(d), "l"(s), "r"(p ? 4 : 0));
}
#define CPCOMMIT() asm volatile("cp.async.commit_group;")
#define CPWAIT0()  asm volatile("cp.async.wait_group 0;")

// ---------------------------------------------------------------------------
// Kernel 1: phi_prob = sigmoid(phi)
// ---------------------------------------------------------------------------
__global__ void sigmoid_kernel(const float4* __restrict__ phi,
                               float4* __restrict__ out) {
    int i = blockIdx.x * blockDim.x + threadIdx.x;
    if (i < (K_ * D_ * T_) / 4) {
        float4 v = phi[i];
        v.x = __fdividef(1.0f, 1.0f + __expf(-v.x));
        v.y = __fdividef(1.0f, 1.0f + __expf(-v.y));
        v.z = __fdividef(1.0f, 1.0f + __expf(-v.z));
        v.w = __fdividef(1.0f, 1.0f + __expf(-v.w));
        out[i] = v;
    }
}

// ---------------------------------------------------------------------------
// Kernel 2: theta = softmax_K(lambda)
// ---------------------------------------------------------------------------
__global__ __launch_bounds__(256)
void softmax_kernel(const float* __restrict__ lam,
                    float* __restrict__ theta) {
    int idx = blockIdx.x * 256 + threadIdx.x;
    if (idx >= N_ * T_) return;
    int n = idx / T_;
    int t = idx - n * T_;
    const float* src = lam + n * KT_ + t;
    float v[K_];
    #pragma unroll
    for (int k = 0; k < K_; ++k) v[k] = src[k * T_];
    float m = v[0];
    #pragma unroll
    for (int k = 1; k < K_; ++k) m = fmaxf(m, v[k]);
    float s = 0.0f;
    #pragma unroll
    for (int k = 0; k < K_; ++k) { v[k] = __expf(v[k] - m); s += v[k]; }
    float inv = __fdividef(1.0f, s);
    float* dst = theta + n * KT_ + t;
    #pragma unroll
    for (int k = 0; k < K_; ++k) dst[k * T_] = v[k] * inv;
}

// ---------------------------------------------------------------------------
// theta quarter issue: 2 or 3 x 16B cp.async per thread
//   thread's chunks share (ni, j); kk = bk + 2r  (bk = tid>>7)
// ---------------------------------------------------------------------------
__device__ __forceinline__ void issue_quarter(
    uint32_t ubuf, const float* p0, int n0, int qk,
    int ni, int bk, uint32_t dst0, bool pv) {
    const float* s = p0 + n0 * KT_ + qk * (KQ * T_);
    bool pr = pv && (n0 + ni < N_);
    cpa16(ubuf + dst0,        s,       pr);   // kk = bk
    cpa16(ubuf + dst0 + 4096, s + 200, pr);   // kk = bk+2
    if (bk == 0)
        cpa16(ubuf + dst0 + 8192, s + 400, pr);  // kk = 4
}

// ---------------------------------------------------------------------------
// Kernel 3: pi = clip(mask * (theta @ phi_prob))
//   R12 GEMM body (scalar-t lanes, f32x2 over d-pairs) + quarter-K cp.async
//   double buffer -> 61KB smem -> 3 blocks/SM (24 warps).
// ---------------------------------------------------------------------------
__global__ __launch_bounds__(NTB, 3)
void gemm_kernel(const float* __restrict__ theta_g,
                 const float* __restrict__ phip,
                 const int*   __restrict__ evt,
                 float*       __restrict__ pi) {
    extern __shared__ float smem[];
    float*  s_thA = smem;                                   // [KQ][NT][TC]
    float*  s_thB = smem + TH_Q_F;                          // [KQ][NT][TC]
    float2* s_ph  = (float2*)(smem + 2 * TH_Q_F);           // [K][DT/2][TC]
    int*    s_ev  = (int*)(smem + 2 * TH_Q_F + PH_F2 * 2);  // [NT][DT]

    const uint32_t u_thA = (uint32_t)__cvta_generic_to_shared(s_thA);
    const uint32_t u_thB = (uint32_t)__cvta_generic_to_shared(s_thB);
    const uint32_t u_ev  = (uint32_t)__cvta_generic_to_shared(s_ev);

    const int tid = threadIdx.x;
    const int d0 = blockIdx.x * DT;
    const int t0 = blockIdx.y * TC;

    // ---- phi tile: load once (d-pairs interleaved as float2) ----
    #pragma unroll
    for (int r = 0; r < 5; ++r) {
        int f  = tid + r * NTB;          // 0..1279
        int j  = f & 7;
        int dp = (f >> 3) & 7;
        int k  = f >> 6;                 // 0..19
        int t  = t0 + 4 * j;
        float4 a = make_float4(0.f, 0.f, 0.f, 0.f);
        float4 b = a;
        if (t < T_) {
            const float* base = phip + k * (D_ * T_) + (d0 + 2 * dp) * T_ + t;
            a = *reinterpret_cast<const float4*>(base);
            b = *reinterpret_cast<const float4*>(base + T_);
        }
        float2* dst = &s_ph[(k * (DT / 2) + dp) * TC + 4 * j];
        dst[0] = make_float2(a.x, b.x);
        dst[1] = make_float2(a.y, b.y);
        dst[2] = make_float2(a.z, b.z);
        dst[3] = make_float2(a.w, b.w);
    }

    // ---- theta chunk descriptors (scalar form) ----
    const int  ni  = (tid >> 3) & 15;
    const int  jj  = tid & 7;
    const int  bk  = tid >> 7;                       // 0 or 1
    const bool tvj = (t0 + 4 * jj < T_);
    const float*   p0   = theta_g + ni * KT_ + bk * T_ + t0 + 4 * jj;
    const uint32_t dst0 = (uint32_t)(bk * 2048 + ni * 128 + 16 * jj);
    const int eni = tid >> 4;
    const int edd = tid & 15;

    const int w    = tid >> 5;
    const int lane = tid & 31;       // lane == t
    const int nb   = (w >> 1) * 4;   // 0,4,8,12
    const int pb   = (w & 1) * 4;    // 0 or 4
    const int t    = t0 + lane;
    const bool tvl = (t < T_);

    // ---- prologue: issue quarter 0 of first tile into A ----
    issue_quarter(u_thA, p0, blockIdx.z * NT, 0, ni, bk, dst0, tvj);
    CPCOMMIT();

    for (int s = 0; s < STEPS; ++s) {
        int nt = blockIdx.z + s * ZSPLIT;
        if (nt >= NTILES) break;
        int n0  = nt * NT;
        int ntn = nt + ZSPLIT;
        bool nextv = (ntn < NTILES);

        unsigned long long acc[4][4];
        #pragma unroll
        for (int i = 0; i < 4; ++i)
            #pragma unroll
            for (int p = 0; p < 4; ++p) acc[i][p] = 0ULL;

        #pragma unroll
        for (int q = 0; q < 4; ++q) {
            CPWAIT0();           // quarter q data arrived
            __syncthreads();     // visible to all; target buffer free

            // issue quarter q+1 (q=3 -> next step's quarter 0)
            uint32_t tgt = ((q + 1) & 1) ? u_thB : u_thA;
            if (q < 3)
                issue_quarter(tgt, p0, n0, q + 1, ni, bk, dst0, tvj);
            else
                issue_quarter(tgt, p0, ntn * NT, 0, ni, bk, dst0,
                              tvj && nextv);
            if (q == 0)
                cpa4(u_ev + (uint32_t)(eni * DT + edd) * 4,
                     evt + (size_t)(n0 + eni) * D_ + d0 + edd,
                     n0 + eni < N_);
            CPCOMMIT();

            // ---- GEMM quarter q: k = q*5 .. q*5+4 ----
            const float* thq = ((q & 1) ? s_thB : s_thA);
            #pragma unroll
            for (int kh = 0; kh < KQ; ++kh) {
                unsigned long long a2[4];
                const float* th = &thq[(kh * NT + nb) * TC + lane];
                #pragma unroll
                for (int i = 0; i < 4; ++i) {
                    float a = th[i * TC];
                    asm("mov.b64 %0, {%1, %1};" : "=l"(a2[i]) : "f"(a));
                }
                unsigned long long b2[4];
                const float2* ph = &s_ph[((q * KQ + kh) * (DT / 2) + pb) * TC + lane];
                #pragma unroll
                for (int p = 0; p < 4; ++p)
                    b2[p] = *reinterpret_cast<const unsigned long long*>(&ph[p * TC]);
                #pragma unroll
                for (int i = 0; i < 4; ++i)
                    #pragma unroll
                    for (int p = 0; p < 4; ++p)
                        asm("fma.rn.f32x2 %0, %1, %2, %0;"
                            : "+l"(acc[i][p]) : "l"(a2[i]), "l"(b2[p]));
            }
        }

        // ---- epilogue: mask, clip, streaming stores ----
        #pragma unroll
        for (int i = 0; i < 4; ++i) {
            int n = n0 + nb + i;
            if (n >= N_) continue;
            float* prow = pi + (size_t)n * (D_ * T_);
            #pragma unroll
            for (int p = 0; p < 4; ++p) {
                float v0, v1;
                asm("mov.b64 {%0, %1}, %2;" : "=f"(v0), "=f"(v1)
                    : "l"(acc[i][p]));
                int c  = (pb + p) * 2;
                int e0 = s_ev[(nb + i) * DT + c];
                int e1 = s_ev[(nb + i) * DT + c + 1];
                v0 = (t <= e0) ? v0 : 0.0f;
                v1 = (t <= e1) ? v1 : 0.0f;
                v0 = fminf(fmaxf(v0, EPSV), 1.0f - EPSV);
                v1 = fminf(fmaxf(v1, EPSV), 1.0f - EPSV);
                if (tvl) {
                    __stcs(&prow[(d0 + c) * T_ + t], v0);
                    __stcs(&prow[(d0 + c + 1) * T_ + t], v1);
                }
            }
        }
    }
    CPWAIT0();   // drain stray prefetch before CTA exit
}

// ---------------------------------------------------------------------------
// Launch
// ---------------------------------------------------------------------------
extern "C" void kernel_launch(void* const* d_in, const int* in_sizes, int n_in,
                              void* d_out, int out_size) {
    const float* lam = (const float*)d_in[0];  // [N,K,T] f32
    const float* phi = (const float*)d_in[1];  // [K,D,T] f32
    const int*   evt = (const int*)d_in[2];    // [N,D]   i32

    const long long PI_SZ  = (long long)N_ * D_ * T_;
    const long long TH_SZ  = (long long)N_ * K_ * T_;
    const long long PHP_SZ = (long long)K_ * D_ * T_;

    float* out   = (float*)d_out;
    float* pi    = out;
    float* theta = out + PI_SZ;
    float* phip  = out + PI_SZ + TH_SZ;

    const long long osz = (long long)out_size;
    if (osz < PI_SZ + TH_SZ)
        cudaGetSymbolAddress((void**)&theta, g_theta_scratch);
    if (osz < PI_SZ + TH_SZ + PHP_SZ)
        cudaGetSymbolAddress((void**)&phip, g_phip_scratch);

    // 1) phi_prob = sigmoid(phi)
    int nvec = (K_ * D_ * T_) / 4;
    sigmoid_kernel<<<(nvec + 255) / 256, 256>>>((const float4*)phi,
                                                (float4*)phip);

    // 2) theta = softmax(lambda)
    int npts = N_ * T_;
    softmax_kernel<<<(npts + 255) / 256, 256>>>(lam, theta);

    // 3) pi = mask*clip(theta @ phi_prob)
    cudaFuncSetAttribute(gemm_kernel,
                         cudaFuncAttributeMaxDynamicSharedMemorySize,
                         SMEM_BYTES);
    dim3 grid(D_ / DT, (T_ + TC - 1) / TC, ZSPLIT);  // 8 x 4 x 13 = 416
    gemm_kernel<<<grid, NTB, SMEM_BYTES>>>(theta, phip, evt, pi);
}

// round 15
// speedup vs baseline: 1.5297x; 1.1302x over previous
#include <cuda_runtime.h>
#include <cstdint>

// Problem constants
#define N_   5000
#define D_   128
#define T_   100
#define K_   20
#define KQ   5             // quarter-K pipeline granularity
#define EPSV 1e-8f
#define KT_  (K_ * T_)

// GEMM tiling: block step = 32n x 16d x 32t
#define NT 32
#define DT 16
#define TC 32
#define NTB 256
#define NTILES 157         // ceil(5000/32)
#define ZSPLIT 9           // 8 x 4 x 9 = 288 blocks = one wave @ 2/SM
#define STEPS  18          // ceil(157/9)

// smem: thA/thB [KQ][NT][TC] f32 (20KB each) + ph [K][DT/2][TC] f2 (40KB) + ev
#define TH_Q_F (KQ * NT * TC)            // 5120 floats
#define PH_F2  (K_ * (DT / 2) * TC)      // 5120 float2
#define SMEM_BYTES (TH_Q_F * 4 * 2 + PH_F2 * 8 + NT * DT * 4)   // 82.9KB

__device__ float g_phip_scratch[K_ * D_ * T_];
__device__ float g_theta_scratch[N_ * K_ * T_];

// ---- cp.async helpers ----
__device__ __forceinline__ void cpa16(uint32_t d, const float* s, bool p) {
    asm volatile("cp.async.cg.shared.global [%0], [%1], 16, %2;"
                 :: "r"(d), "l"(s), "r"(p ? 16 : 0));
}
__device__ __forceinline__ void cpa8(uint32_t d, const int* s, bool p) {
    asm volatile("cp.async.ca.shared.global [%0], [%1], 8, %2;"
                 :: "r"(d), "l"(s), "r"(p ? 8 : 0));
}
#define CPCOMMIT() asm volatile("cp.async.commit_group;")
#define CPWAIT0()  asm volatile("cp.async.wait_group 0;")

// ---------------------------------------------------------------------------
// Kernel 1: phi_prob = sigmoid(phi)
// ---------------------------------------------------------------------------
__global__ void sigmoid_kernel(const float4* __restrict__ phi,
                               float4* __restrict__ out) {
    int i = blockIdx.x * blockDim.x + threadIdx.x;
    if (i < (K_ * D_ * T_) / 4) {
        float4 v = phi[i];
        v.x = __fdividef(1.0f, 1.0f + __expf(-v.x));
        v.y = __fdividef(1.0f, 1.0f + __expf(-v.y));
        v.z = __fdividef(1.0f, 1.0f + __expf(-v.z));
        v.w = __fdividef(1.0f, 1.0f + __expf(-v.w));
        out[i] = v;
    }
}

// ---------------------------------------------------------------------------
// Kernel 2: theta = softmax_K(lambda)
// ---------------------------------------------------------------------------
__global__ __launch_bounds__(256)
void softmax_kernel(const float* __restrict__ lam,
                    float* __restrict__ theta) {
    int idx = blockIdx.x * 256 + threadIdx.x;
    if (idx >= N_ * T_) return;
    int n = idx / T_;
    int t = idx - n * T_;
    const float* src = lam + n * KT_ + t;
    float v[K_];
    #pragma unroll
    for (int k = 0; k < K_; ++k) v[k] = src[k * T_];
    float m = v[0];
    #pragma unroll
    for (int k = 1; k < K_; ++k) m = fmaxf(m, v[k]);
    float s = 0.0f;
    #pragma unroll
    for (int k = 0; k < K_; ++k) { v[k] = __expf(v[k] - m); s += v[k]; }
    float inv = __fdividef(1.0f, s);
    float* dst = theta + n * KT_ + t;
    #pragma unroll
    for (int k = 0; k < K_; ++k) dst[k * T_] = v[k] * inv;
}

// ---------------------------------------------------------------------------
// Kernel 3: pi = clip(mask * (theta @ phi_prob))
//   Crossbar-balanced thread tile 8n x 4 d-pairs: per k/warp 16 phases per
//   2048 FMA (1 phase/128FMA). Quarter-K cp.async double buffer; phi once.
//   Thread's 5 theta chunks: (ni=tid>>3, j=tid&7), kk = r  -> scalar descs.
// ---------------------------------------------------------------------------
__global__ __launch_bounds__(NTB, 2)
void gemm_kernel(const float* __restrict__ theta_g,
                 const float* __restrict__ phip,
                 const int*   __restrict__ evt,
                 float*       __restrict__ pi) {
    extern __shared__ float smem[];
    float*  s_thA = smem;                                   // [KQ][NT][TC]
    float*  s_thB = smem + TH_Q_F;                          // [KQ][NT][TC]
    float2* s_ph  = (float2*)(smem + 2 * TH_Q_F);           // [K][DT/2][TC]
    int*    s_ev  = (int*)(smem + 2 * TH_Q_F + PH_F2 * 2);  // [NT][DT]

    const uint32_t u_thA = (uint32_t)__cvta_generic_to_shared(s_thA);
    const uint32_t u_thB = (uint32_t)__cvta_generic_to_shared(s_thB);
    const uint32_t u_ev  = (uint32_t)__cvta_generic_to_shared(s_ev);

    const int tid = threadIdx.x;
    const int d0 = blockIdx.x * DT;
    const int t0 = blockIdx.y * TC;

    // ---- phi tile: load once (d-pairs interleaved as float2) ----
    #pragma unroll
    for (int r = 0; r < 5; ++r) {
        int f  = tid + r * NTB;          // 0..1279
        int j  = f & 7;
        int dp = (f >> 3) & 7;
        int k  = f >> 6;                 // 0..19
        int t  = t0 + 4 * j;
        float4 a = make_float4(0.f, 0.f, 0.f, 0.f);
        float4 b = a;
        if (t < T_) {
            const float* base = phip + k * (D_ * T_) + (d0 + 2 * dp) * T_ + t;
            a = *reinterpret_cast<const float4*>(base);
            b = *reinterpret_cast<const float4*>(base + T_);
        }
        float2* dst = &s_ph[(k * (DT / 2) + dp) * TC + 4 * j];
        dst[0] = make_float2(a.x, b.x);
        dst[1] = make_float2(a.y, b.y);
        dst[2] = make_float2(a.z, b.z);
        dst[3] = make_float2(a.w, b.w);
    }

    // ---- theta chunk descriptors: thread owns (ni, t-quad j), kk = r ----
    const int  ni  = tid >> 3;                   // 0..31
    const int  jj  = tid & 7;                    // t-quad
    const bool tvj = (t0 + 4 * jj < T_);
    const float*   pth  = theta_g + ni * KT_ + t0 + 4 * jj;   // + n0*KT + (q*5+r)*T
    const uint32_t dth  = (uint32_t)(ni * 128 + 16 * jj);     // + r*4096
    // evt: int2 per thread: [ni][2*jj .. 2*jj+1]
    const uint32_t dev  = (uint32_t)(ni * 64 + 8 * jj);

    const int w    = tid >> 5;
    const int lane = tid & 31;       // lane == t
    const int nb   = (w >> 1) * 8;   // 0,8,16,24
    const int pb   = (w & 1) * 4;    // 0 or 4
    const int t    = t0 + lane;
    const bool tvl = (t < T_);

    // ---- prologue: issue quarter 0 of first tile into A ----
    {
        int n0 = blockIdx.z * NT;
        bool pv = tvj && (n0 + ni < N_);
        const float* s = pth + n0 * KT_;
        #pragma unroll
        for (int r = 0; r < 5; ++r)
            cpa16(u_thA + dth + r * 4096, s + r * T_, pv);
        CPCOMMIT();
    }

    for (int st = 0; st < STEPS; ++st) {
        int nt = blockIdx.z + st * ZSPLIT;
        if (nt >= NTILES) break;
        int n0  = nt * NT;
        int ntn = nt + ZSPLIT;
        const bool curv  = tvj && (n0 + ni < N_);
        const bool nextv = tvj && (ntn < NTILES) && (ntn * NT + ni < N_);

        unsigned long long acc[8][4];
        #pragma unroll
        for (int i = 0; i < 8; ++i)
            #pragma unroll
            for (int p = 0; p < 4; ++p) acc[i][p] = 0ULL;

        #pragma unroll
        for (int q = 0; q < 4; ++q) {
            CPWAIT0();           // quarter q data arrived
            __syncthreads();     // visible; target buffer free

            // issue quarter q+1 (q=3 -> next tile's quarter 0)
            uint32_t tgt = ((q + 1) & 1) ? u_thB : u_thA;
            if (q < 3) {
                const float* s = pth + n0 * KT_ + (q + 1) * (KQ * T_);
                #pragma unroll
                for (int r = 0; r < 5; ++r)
                    cpa16(tgt + dth + r * 4096, s + r * T_, curv);
            } else {
                const float* s = pth + ntn * NT * KT_;
                #pragma unroll
                for (int r = 0; r < 5; ++r)
                    cpa16(tgt + dth + r * 4096, s + r * T_, nextv);
            }
            if (q == 0)
                cpa8(u_ev + dev,
                     evt + (size_t)(n0 + ni) * D_ + d0 + 2 * jj,
                     n0 + ni < N_);
            CPCOMMIT();

            // ---- GEMM quarter q: k = q*5 .. q*5+4 ----
            const float* thq = ((q & 1) ? s_thB : s_thA);
            #pragma unroll
            for (int kh = 0; kh < KQ; ++kh) {
                unsigned long long b2[4];
                const float2* ph = &s_ph[((q * KQ + kh) * (DT / 2) + pb) * TC + lane];
                #pragma unroll
                for (int p = 0; p < 4; ++p)
                    b2[p] = *reinterpret_cast<const unsigned long long*>(&ph[p * TC]);
                const float* th = &thq[(kh * NT + nb) * TC + lane];
                #pragma unroll
                for (int i = 0; i < 8; ++i) {
                    float a = th[i * TC];
                    unsigned long long a2;
                    asm("mov.b64 %0, {%1, %1};" : "=l"(a2) : "f"(a));
                    #pragma unroll
                    for (int p = 0; p < 4; ++p)
                        asm("fma.rn.f32x2 %0, %1, %2, %0;"
                            : "+l"(acc[i][p]) : "l"(a2), "l"(b2[p]));
                }
            }
        }

        // ---- epilogue: mask, clip, streaming stores ----
        #pragma unroll
        for (int i = 0; i < 8; ++i) {
            int n = n0 + nb + i;
            if (n >= N_) continue;
            float* prow = pi + (size_t)n * (D_ * T_);
            #pragma unroll
            for (int p = 0; p < 4; ++p) {
                float v0, v1;
                asm("mov.b64 {%0, %1}, %2;" : "=f"(v0), "=f"(v1)
                    : "l"(acc[i][p]));
                int c  = (pb + p) * 2;
                int e0 = s_ev[(nb + i) * DT + c];
                int e1 = s_ev[(nb + i) * DT + c + 1];
                v0 = (t <= e0) ? v0 : 0.0f;
                v1 = (t <= e1) ? v1 : 0.0f;
                v0 = fminf(fmaxf(v0, EPSV), 1.0f - EPSV);
                v1 = fminf(fmaxf(v1, EPSV), 1.0f - EPSV);
                if (tvl) {
                    __stcs(&prow[(d0 + c) * T_ + t], v0);
                    __stcs(&prow[(d0 + c + 1) * T_ + t], v1);
                }
            }
        }
    }
    CPWAIT0();   // drain stray prefetch before CTA exit
}

// ---------------------------------------------------------------------------
// Launch
// ---------------------------------------------------------------------------
extern "C" void kernel_launch(void* const* d_in, const int* in_sizes, int n_in,
                              void* d_out, int out_size) {
    const float* lam = (const float*)d_in[0];  // [N,K,T] f32
    const float* phi = (const float*)d_in[1];  // [K,D,T] f32
    const int*   evt = (const int*)d_in[2];    // [N,D]   i32

    const long long PI_SZ  = (long long)N_ * D_ * T_;
    const long long TH_SZ  = (long long)N_ * K_ * T_;
    const long long PHP_SZ = (long long)K_ * D_ * T_;

    float* out   = (float*)d_out;
    float* pi    = out;
    float* theta = out + PI_SZ;
    float* phip  = out + PI_SZ + TH_SZ;

    const long long osz = (long long)out_size;
    if (osz < PI_SZ + TH_SZ)
        cudaGetSymbolAddress((void**)&theta, g_theta_scratch);
    if (osz < PI_SZ + TH_SZ + PHP_SZ)
        cudaGetSymbolAddress((void**)&phip, g_phip_scratch);

    // 1) phi_prob = sigmoid(phi)
    int nvec = (K_ * D_ * T_) / 4;
    sigmoid_kernel<<<(nvec + 255) / 256, 256>>>((const float4*)phi,
                                                (float4*)phip);

    // 2) theta = softmax(lambda)
    int npts = N_ * T_;
    softmax_kernel<<<(npts + 255) / 256, 256>>>(lam, theta);

    // 3) pi = mask*clip(theta @ phi_prob)
    cudaFuncSetAttribute(gemm_kernel,
                         cudaFuncAttributeMaxDynamicSharedMemorySize,
                         SMEM_BYTES);
    dim3 grid(D_ / DT, (T_ + TC - 1) / TC, ZSPLIT);  // 8 x 4 x 9 = 288
    gemm_kernel<<<grid, NTB, SMEM_BYTES>>>(theta, phip, evt, pi);
}